// round 17
// baseline (speedup 1.0000x reference)
#include <cuda_runtime.h>
#include <cuda_fp16.h>
#include <math.h>
#include <stdint.h>

#define NNODES 500
#define NP     512
#define NFEAT  32768
#define NEDGE  16000
#define NSCALE 4
#define NCOEF 9
#define DCTN 128

// ---------------- device scratch (static, allocation-free) ----------------
__device__ float g_M [NP * NP];            // M = (L - c0 I)/h  (persists)
__device__ float g_Ta[NP * NP];            // T2
__device__ float g_Tb[NP * NP];            // T3
__device__ float g_Tc[NP * NP];            // T4
__device__ float g_W [NSCALE * NP * NP];   // T5..T8
__device__ float g_deg [NP];
__device__ float g_rad [NP];               // Gershgorin radius (atomic, inflated-safe)
__device__ float g_c0h[2];
__device__ float g_coef[2 * NCOEF];        // set 0: s0 (W 0.5), set 1: 2*s0 (W 1)

// Packed, pre-swizzled (SW128) fp16 hi/lo operand tiles.
// slots 0..3: W(0.5),W(1),W(2),W(4); slots 4..7: M,T2,T3,T4
#define NSLOT 8
__device__ __half g_Ah[NSLOT * 4 * 8 * 8192];
__device__ __half g_Al[NSLOT * 4 * 8 * 8192];
__device__ __half g_Bh[256 * 8 * 8192];

// pack one fp32 value into the SW128 fp16 hi/lo tile layout for a slot
__device__ __forceinline__ void packA2(int slot, int m, int k, float v) {
    int tile = ((slot * 4 + (m >> 7)) * 8) + (k >> 6);
    int off = (m & 127) * 128 + (k & 63) * 2;
    off ^= (off >> 3) & 0x70;
    int idx = tile * 8192 + (off >> 1);
    __half h = __float2half(v);
    g_Ah[idx] = h;
    g_Al[idx] = __float2half(v - __half2float(h));
}

// ---------------- graph / Laplacian build ----------------
__global__ void k_zero() {
    int i = blockIdx.x * blockDim.x + threadIdx.x;
    if (i < NP * NP) g_M[i] = 0.f;
    if (i < NP) { g_deg[i] = 0.f; g_rad[i] = 0.f; }
}

__global__ void k_degree(const int* __restrict__ ei) {
    int e = blockIdx.x * blockDim.x + threadIdx.x;
    if (e < NEDGE) atomicAdd(&g_deg[ei[NEDGE + e]], 1.0f);
}

// adj write + atomic Gershgorin radius accumulation (duplicates inflate the
// radius, which only widens the enclosure — still valid)
__global__ void k_adj(const int* __restrict__ ei) {
    int e = blockIdx.x * blockDim.x + threadIdx.x;
    if (e < NEDGE) {
        int s = ei[e], d = ei[NEDGE + e];
        float v = -rsqrtf(fmaxf(g_deg[s], 1.0f)) * rsqrtf(fmaxf(g_deg[d], 1.0f));
        g_M[s * NP + d] = v;
        g_M[d * NP + s] = v;
        float av = fabsf(v);
        atomicAdd(&g_rad[s], av);
        atomicAdd(&g_rad[d], av);
    }
}

// Diagonal fixup + spectral bounds in one tiny block:
// c = M[i][i] + 1 (i<NNODES); lo/hi = c -/+ rad; reduce to c0,h.
__global__ void __launch_bounds__(512) k_bnds() {
    __shared__ float slo[512], shi[512];
    int i = threadIdx.x;
    float cold = g_M[i * NP + i];
    float c = cold + ((i < NNODES) ? 1.f : 0.f);
    g_M[i * NP + i] = c;
    float r = g_rad[i];
    slo[i] = c - r;
    shi[i] = c + r;
    __syncthreads();
    for (int s = 256; s > 0; s >>= 1) {
        if (i < s) {
            slo[i] = fminf(slo[i], slo[i + s]);
            shi[i] = fmaxf(shi[i], shi[i + s]);
        }
        __syncthreads();
    }
    if (i == 0) {
        float lo = slo[0], hi = shi[0];
        float c0 = 0.5f * (hi + lo);
        float h  = 0.5f * (hi - lo);
        h = fmaxf(h, 1e-4f) * 1.0001f;
        g_c0h[0] = c0;
        g_c0h[1] = h;
    }
}

// Chebyshev coefs of exp(-s(c0 + h t)) for s in {s0, 2*s0}; grid (NCOEF, 2).
__global__ void __launch_bounds__(DCTN) k_coef(const float* __restrict__ scales) {
    __shared__ double red[DCTN];
    int j = threadIdx.x;
    int k = blockIdx.x;
    int set = blockIdx.y;
    const double PI = 3.14159265358979323846;
    double s0 = (double)scales[0] * (double)(set + 1);
    double c0 = (double)g_c0h[0];
    double h  = (double)g_c0h[1];
    double th = PI * (j + 0.5) / (double)DCTN;
    red[j] = exp(-s0 * (c0 + h * cos(th))) * cos((double)k * th);
    __syncthreads();
    for (int s = DCTN / 2; s > 0; s >>= 1) {
        if (j < s) red[j] += red[j + s];
        __syncthreads();
    }
    if (j == 0)
        g_coef[set * NCOEF + k] =
            (float)(red[0] * ((k == 0) ? 1.0 : 2.0) / (double)DCTN);
}

// M = (L - c0 I)/h in place; also packs slot 4 (hi/lo)
__global__ void k_scaleM() {
    int i = blockIdx.x * blockDim.x + threadIdx.x;
    if (i < NP * NP) {
        int r = i >> 9, c = i & (NP - 1);
        float c0 = g_c0h[0], h = g_c0h[1];
        float diag = (r == c) ? 1.f : 0.f;
        float m = (g_M[i] - c0 * diag) / h;
        g_M[i] = m;
        packA2(4, r, c, m);
    }
}

// W(0.5)->slot0 and W(1)->slot1 from the same T basis (two coef sets)
__global__ void k_sum() {
    int i = blockIdx.x * blockDim.x + threadIdx.x;
    if (i >= NP * NP) return;
    int r = i >> 9, c = i & (NP - 1);
    float tv[NCOEF];
    tv[0] = (r == c) ? 1.f : 0.f;
    tv[1] = g_M[i];
    tv[2] = g_Ta[i];
    tv[3] = g_Tb[i];
    tv[4] = g_Tc[i];
    tv[5] = g_W[i];
    tv[6] = g_W[NP * NP + i];
    tv[7] = g_W[2 * NP * NP + i];
    tv[8] = g_W[3 * NP * NP + i];
    float v0 = 0.f, v1 = 0.f;
#pragma unroll
    for (int k = 0; k < NCOEF; k++) {
        v0 += g_coef[k] * tv[k];
        v1 += g_coef[NCOEF + k] * tv[k];
    }
    packA2(0, r, c, v0);
    packA2(1, r, c, v1);
}

// ---------------- x transpose -> fp16 SW128 tiles ----------------
__global__ void __launch_bounds__(256) k_convX(const float* __restrict__ x) {
    __shared__ float t[32][132];
    int nt = blockIdx.x;
    int kb = blockIdx.y;
    int tid = threadIdx.x;

#pragma unroll
    for (int it = 0; it < 4; it++) {
        int f = tid + it * 256;
        int row = f >> 5, c4 = f & 31;
        int kg = kb * 32 + row;
        float4 v = make_float4(0.f, 0.f, 0.f, 0.f);
        if (kg < NNODES)
            v = *(const float4*)(x + (size_t)kg * NFEAT + nt * 128 + c4 * 4);
        t[row][c4 * 4 + 0] = v.x;
        t[row][c4 * 4 + 1] = v.y;
        t[row][c4 * 4 + 2] = v.z;
        t[row][c4 * 4 + 3] = v.w;
    }
    __syncthreads();

    size_t tile_bytes = (size_t)(nt * 8 + (kb >> 1)) * 16384;
    int halfk = (kb & 1) * 32;
    char* bh = (char*)g_Bh + tile_bytes;

#pragma unroll
    for (int it = 0; it < 2; it++) {
        int j = tid + it * 256;
        int n = j >> 2, q = j & 3;
        __align__(16) __half hs[8];
#pragma unroll
        for (int e = 0; e < 8; e++)
            hs[e] = __float2half(t[q * 8 + e][n]);
        int off = n * 128 + (halfk + q * 8) * 2;
        off ^= (off >> 3) & 0x70;
        *(uint4*)(bh + off) = *(const uint4*)hs;
    }
}

// ---------------- HMMA helpers ----------------
__device__ __forceinline__ void ldmx4(uint32_t* r, uint32_t addr) {
    asm volatile("ldmatrix.sync.aligned.m8n8.x4.shared.b16 {%0,%1,%2,%3}, [%4];"
                 : "=r"(r[0]), "=r"(r[1]), "=r"(r[2]), "=r"(r[3]) : "r"(addr));
}
__device__ __forceinline__ void mma16816(float* c, const uint32_t* a,
                                         const uint32_t* b) {
    asm volatile(
        "mma.sync.aligned.m16n8k16.row.col.f32.f16.f16.f32 "
        "{%0,%1,%2,%3}, {%4,%5,%6,%7}, {%8,%9}, {%0,%1,%2,%3};"
        : "+f"(c[0]), "+f"(c[1]), "+f"(c[2]), "+f"(c[3])
        : "r"(a[0]), "r"(a[1]), "r"(a[2]), "r"(a[3]), "r"(b[0]), "r"(b[1]));
}
__device__ __forceinline__ void cpasync16(uint32_t dst, const void* src) {
    asm volatile("cp.async.cg.shared.global [%0], [%1], 16;"
                 :: "r"(dst), "l"(src) : "memory");
}

// ---------------- generalized 512x512 HMMA 3-term GEMM on packed slots ----
struct MMJob {
    int sa, sb;
    const float* Q;
    float* D;
    int qid;
    int so;     // -1 = no pack
    int mode;   // 0: D=2AB-Q (+pack), 1: pack = AB
};

#define SQ_STAGE  32768
#define SQ_NSTAGE 4
#define SQ_SMEM   (SQ_NSTAGE * SQ_STAGE)

__global__ void __launch_bounds__(256, 1) k_mm3(MMJob j0, MMJob j1,
                                                MMJob j2, MMJob j3) {
    MMJob J = (blockIdx.z == 0) ? j0 : (blockIdx.z == 1) ? j1
            : (blockIdx.z == 2) ? j2 : j3;

    extern __shared__ __align__(1024) char smem[];
    uint32_t sb = (uint32_t)__cvta_generic_to_shared(smem);
    int tid = threadIdx.x, wid = tid >> 5, lid = tid & 31;
    int m0 = blockIdx.y * 64, n0 = blockIdx.x * 64;
    int wm = wid >> 2, wn = wid & 3;   // 2m x 4n warps, warp tile 32m x 16n

    const char* Ahb = (const char*)g_Ah;
    const char* Alb = (const char*)g_Al;

    float acc[2][2][4] = {};

    auto issue = [&](int c) {
        uint32_t dst = sb + (c & (SQ_NSTAGE - 1)) * SQ_STAGE;
        size_t baseA = ((size_t)((J.sa * 4 + (m0 >> 7)) * 8 + c)) * 16384 +
                       (size_t)(m0 & 127) * 128;
        size_t baseB = ((size_t)((J.sb * 4 + (n0 >> 7)) * 8 + c)) * 16384 +
                       (size_t)(n0 & 127) * 128;
#pragma unroll
        for (int it = 0; it < 8; it++) {
            int line = tid + it * 256;
            int reg = line >> 9;                // 0:Ah 1:Al 2:Bh 3:Bl
            uint32_t o = (uint32_t)(line & 511) * 16;
            const char* src;
            if (reg == 0)      src = Ahb + baseA + o;
            else if (reg == 1) src = Alb + baseA + o;
            else if (reg == 2) src = Ahb + baseB + o;
            else               src = Alb + baseB + o;
            cpasync16(dst + (uint32_t)line * 16, src);
        }
        asm volatile("cp.async.commit_group;");
    };

    issue(0);
    issue(1);
    issue(2);

    for (int c = 0; c < 8; c++) {
        asm volatile("cp.async.wait_group 2;");
        __syncthreads();

        uint32_t base = sb + (c & (SQ_NSTAGE - 1)) * SQ_STAGE;
        uint32_t sAh = base, sAl = base + 8192;
        uint32_t sBh = base + 16384, sBl = base + 24576;

#pragma unroll
        for (int kk = 0; kk < 4; kk++) {
            uint32_t ah[2][4], al[2][4], bh[4], bl[4];
#pragma unroll
            for (int i = 0; i < 2; i++) {
                uint32_t off = (uint32_t)(wm * 32 + i * 16 + (lid & 15)) * 128 +
                               kk * 32 + (lid >> 4) * 16;
                off ^= (off >> 3) & 0x70;
                ldmx4(ah[i], sAh + off);
                ldmx4(al[i], sAl + off);
            }
            {
                int nl = wn * 16 + ((lid >> 4) & 1) * 8 + (lid & 7);
                uint32_t off = (uint32_t)nl * 128 +
                               kk * 32 + ((lid >> 3) & 1) * 16;
                off ^= (off >> 3) & 0x70;
                ldmx4(bh, sBh + off);
                ldmx4(bl, sBl + off);
            }
#pragma unroll
            for (int i = 0; i < 2; i++) {
#pragma unroll
                for (int j = 0; j < 2; j++) {
                    mma16816(acc[i][j], ah[i], &bh[j * 2]);
                    mma16816(acc[i][j], ah[i], &bl[j * 2]);
                    mma16816(acc[i][j], al[i], &bh[j * 2]);
                }
            }
        }
        if (c + 3 < 8) issue(c + 3);
        else asm volatile("cp.async.commit_group;");
    }

    // epilogue
    int qrow = lid >> 2, qcol = (lid & 3) * 2;
#pragma unroll
    for (int i = 0; i < 2; i++) {
#pragma unroll
        for (int j = 0; j < 2; j++) {
#pragma unroll
            for (int e = 0; e < 4; e++) {
                int m = m0 + wm * 32 + i * 16 + qrow + (e >> 1) * 8;
                int n = n0 + wn * 16 + j * 8 + qcol + (e & 1);
                float v = acc[i][j][e];
                if (J.mode == 0) {
                    int idx = m * NP + n;
                    float q = J.qid ? ((m == n) ? 1.f : 0.f) : J.Q[idx];
                    v = 2.f * v - q;
                    J.D[idx] = v;
                }
                if (J.so >= 0) packA2(J.so, m, n, v);
            }
        }
    }
}

// ---------------- big GEMM: out[s] = W_s @ x via HMMA fp16 ----------------
// CTA tile 128m x 128n, 3-stage cp.async, 2 CTAs/SM (at mma.sync roofline)
#define STAGE_BYTES 32768
#define NSTAGE 3
#define DSMEM_TOTAL (NSTAGE * STAGE_BYTES)

__global__ void __launch_bounds__(256, 2) k_bigmma(float* __restrict__ out) {
    extern __shared__ __align__(1024) char smem[];
    uint32_t sb = (uint32_t)__cvta_generic_to_shared(smem);
    int tid = threadIdx.x, wid = tid >> 5, lid = tid & 31;
    int mt = blockIdx.x & 3, s = blockIdx.x >> 2, nt = blockIdx.y;
    int wm0 = (wid >> 2) * 64;
    int wn0 = (wid & 3) * 32;

    const char* pAh = (const char*)(g_Ah + ((size_t)((s * 4 + mt) * 8)) * 8192);

    float acc[4][4][4] = {};

    auto issue = [&](int c) {
        uint32_t dst = sb + (c % NSTAGE) * STAGE_BYTES;
        size_t aoff = (size_t)c * 16384;
        size_t boff = ((size_t)(nt * 8 + c)) * 16384;
#pragma unroll
        for (int it = 0; it < 4; it++) {
            uint32_t o = (uint32_t)(tid + it * 256) * 16;
            cpasync16(dst + o,         pAh + aoff + o);
            cpasync16(dst + 16384 + o, (const char*)g_Bh + boff + o);
        }
        asm volatile("cp.async.commit_group;");
    };

    issue(0);
    issue(1);

    for (int c = 0; c < 8; c++) {
        asm volatile("cp.async.wait_group 1;");
        __syncthreads();
        if (c + 2 < 8) issue(c + 2);
        else asm volatile("cp.async.commit_group;");

        uint32_t base = sb + (c % NSTAGE) * STAGE_BYTES;
        uint32_t sAh = base, sBh = base + 16384;

#pragma unroll
        for (int kk = 0; kk < 4; kk++) {
            uint32_t ah[4][4], bh[2][4];
#pragma unroll
            for (int i = 0; i < 4; i++) {
                uint32_t off = (uint32_t)(wm0 + i * 16 + (lid & 15)) * 128 +
                               kk * 32 + (lid >> 4) * 16;
                off ^= (off >> 3) & 0x70;
                ldmx4(ah[i], sAh + off);
            }
#pragma unroll
            for (int g = 0; g < 2; g++) {
                int nl = wn0 + g * 16 + ((lid >> 4) & 1) * 8 + (lid & 7);
                uint32_t off = (uint32_t)nl * 128 +
                               kk * 32 + ((lid >> 3) & 1) * 16;
                off ^= (off >> 3) & 0x70;
                ldmx4(bh[g], sBh + off);
            }
#pragma unroll
            for (int i = 0; i < 4; i++) {
#pragma unroll
                for (int j = 0; j < 4; j++) {
                    int g = j >> 1, h = (j & 1) * 2;
                    mma16816(acc[i][j], ah[i], &bh[g][h]);
                }
            }
        }
    }

    // epilogue
    int qrow = lid >> 2, qcol = (lid & 3) * 2;
#pragma unroll
    for (int i = 0; i < 4; i++) {
        int m0g = mt * 128 + wm0 + i * 16 + qrow;
#pragma unroll
        for (int j = 0; j < 4; j++) {
            int n = nt * 128 + wn0 + j * 8 + qcol;
            if (m0g < NNODES) {
                size_t idx = ((size_t)s * NNODES + m0g) * NFEAT + n;
                *(float2*)(out + idx) = make_float2(acc[i][j][0], acc[i][j][1]);
            }
            if (m0g + 8 < NNODES) {
                size_t idx = ((size_t)s * NNODES + m0g + 8) * NFEAT + n;
                *(float2*)(out + idx) = make_float2(acc[i][j][2], acc[i][j][3]);
            }
        }
    }
}

// ---------------- launch (single stream — graph-capture safe) ----------------
extern "C" void kernel_launch(void* const* d_in, const int* in_sizes, int n_in,
                              void* d_out, int out_size) {
    const float* x      = (const float*)d_in[0];
    const int*   ei     = (const int*)d_in[1];
    const float* scales = (const float*)d_in[2];
    float* out = (float*)d_out;

    float *pM, *pTa, *pTb, *pTc, *pW;
    cudaGetSymbolAddress((void**)&pM,  g_M);
    cudaGetSymbolAddress((void**)&pTa, g_Ta);
    cudaGetSymbolAddress((void**)&pTb, g_Tb);
    cudaGetSymbolAddress((void**)&pTc, g_Tc);
    cudaGetSymbolAddress((void**)&pW,  g_W);

    static int smem_set = 0;
    if (!smem_set) {
        cudaFuncSetAttribute(k_bigmma, cudaFuncAttributeMaxDynamicSharedMemorySize,
                             DSMEM_TOTAL);
        cudaFuncSetAttribute(k_mm3, cudaFuncAttributeMaxDynamicSharedMemorySize,
                             SQ_SMEM);
        smem_set = 1;
    }

    const size_t NPNP = (size_t)NP * NP;
    float* pW0 = pW;
    float* pW1 = pW + NPNP;
    float* pW2 = pW + 2 * NPNP;
    float* pW3 = pW + 3 * NPNP;

    // build: zero, degree, adj(+radius), bounds, coefs, scaleM(+pack slot4)
    k_zero<<<(NP * NP + 255) / 256, 256>>>();
    k_degree<<<(NEDGE + 255) / 256, 256>>>(ei);
    k_adj<<<(NEDGE + 255) / 256, 256>>>(ei);
    k_bnds<<<1, 512>>>();
    dim3 gc(NCOEF, 2);
    k_coef<<<gc, DCTN>>>(scales);
    k_scaleM<<<(NP * NP + 255) / 256, 256>>>();

    // x transpose + fp16 pack
    dim3 gx(256, 16);
    k_convX<<<gx, 256>>>(x);

    // Chebyshev via HMMA on packed slots (4=M, 5=T2, 6=T3, 7=T4)
    dim3 gz1(8, 8, 1), gz2(8, 8, 2), gz4(8, 8, 4);
    MMJob JD = {0, 0, nullptr, nullptr, 0, -1, 1};  // dummy filler

    // wave 1: T2 = 2 M M - I  (fp32 Ta + pack slot 5)
    MMJob w1 = {4, 4, nullptr, pTa, 1, 5, 0};
    k_mm3<<<gz1, 256, SQ_SMEM>>>(w1, JD, JD, JD);

    // wave 2: T3 = 2 M T2 - M ; T4 = 2 T2 T2 - I
    MMJob w2a = {4, 5, pM, pTb, 0, 6, 0};
    MMJob w2b = {5, 5, nullptr, pTc, 1, 7, 0};
    k_mm3<<<gz2, 256, SQ_SMEM>>>(w2a, w2b, JD, JD);

    // wave 3: T5 = 2 T2 T3 - M ; T6 = 2 T3 T3 - I ; T7 = 2 T3 T4 - M ; T8 = 2 T4 T4 - I
    MMJob w3a = {5, 6, pM, pW0, 0, -1, 0};
    MMJob w3b = {6, 6, nullptr, pW1, 1, -1, 0};
    MMJob w3c = {6, 7, pM, pW2, 0, -1, 0};
    MMJob w3d = {7, 7, nullptr, pW3, 1, -1, 0};
    k_mm3<<<gz4, 256, SQ_SMEM>>>(w3a, w3b, w3c, w3d);

    // W(0.5) -> slot 0 and W(1) -> slot 1 (dual coefficient sets)
    k_sum<<<(NP * NP + 255) / 256, 256>>>();

    // HMMA squaring ladder: 1 -> 2 -> 4 (slots 1->2->3)
    MMJob q2 = {1, 1, nullptr, nullptr, 0, 2, 1};
    MMJob q3 = {2, 2, nullptr, nullptr, 0, 3, 1};
    k_mm3<<<gz1, 256, SQ_SMEM>>>(q2, JD, JD, JD);
    k_mm3<<<gz1, 256, SQ_SMEM>>>(q3, JD, JD, JD);

    // big HMMA GEMM: blockIdx.x = mt + 4*s (16), blockIdx.y = n tile of 128 (256)
    dim3 gb(16, 256);
    k_bigmma<<<gb, 256, DSMEM_TOTAL>>>(out);
}